// round 1
// baseline (speedup 1.0000x reference)
#include <cuda_runtime.h>
#include <math.h>
#include <stdint.h>

// Problem constants
#define DIMN  2048
#define BATCH 16384

// ---------------------------------------------------------------------------
// Device scratch (static allocation — no runtime allocs allowed)
// ---------------------------------------------------------------------------
__device__ __align__(128) float g_Dt  [DIMN * DIMN];   // Dt[m][k]  = D[k][m]
__device__ __align__(128) float g_Et  [DIMN * DIMN];   // Et[n][k]  = bscale[k]*D[k][n]
__device__ __align__(128) float g_Deff[DIMN * DIMN];   // Deff = D^T S D (symmetric)
__device__ __align__(128) float g_W1e [1024 * DIMN];   // W1e = W1 @ Deff
__device__ __align__(128) float g_h1  [BATCH * 1024];
__device__ __align__(128) float g_h2  [BATCH * 512];
__device__ __align__(128) float g_bscale[DIMN];

// ---------------------------------------------------------------------------
// Band-scale: replicates np.linspace(0, N-1, 31).astype(int64) banding
// ---------------------------------------------------------------------------
__global__ void build_scale_kernel(const float* __restrict__ fw,
                                   const float* __restrict__ kptr)
{
    int idx = blockIdx.x * blockDim.x + threadIdx.x;
    if (idx >= DIMN) return;

    const float kv = *kptr;
    float val = 1.0f;                      // default (index 2047 keeps 1.0)
    const double step = 2047.0 / 30.0;     // numpy linspace delta, double

    #pragma unroll 1
    for (int i = 0; i < 30; i++) {
        int s = (int)(step * (double)i);
        int e = (i == 29) ? 2047 : (int)(step * (double)(i + 1)); // linspace endpoint exact
        if (idx >= s && idx < e) {
            float f;
            if (e <= 30) {  // SPLIT_FREQ
                f = 1.0f + fw[i] * kv * (1.0f - (float)i / 30.0f);
            } else {
                f = 1.0f - fw[i] * kv * (1.0f - (float)(i - 30) / 30.0f);
            }
            val = f;
        }
    }
    g_bscale[idx] = val;
}

// ---------------------------------------------------------------------------
// Build Dt and Et.  D[k][n] = cos(pi*(n+0.5)*k/N) * s[k]
// Angle reduced exactly in integers: cos(pi*q/4096), q = ((2n+1)k) mod 8192.
// q/4096 is exactly representable in fp32 -> cospif gives ~1ulp accuracy,
// matching the float64-built reference matrix.
// ---------------------------------------------------------------------------
__global__ void build_D_kernel()
{
    int idx = blockIdx.x * blockDim.x + threadIdx.x;     // < DIMN*DIMN
    int j  = idx >> 11;          // position index (row of Dt/Et)
    int kk = idx & (DIMN - 1);   // coefficient index (column)

    int q = ((2 * j + 1) * kk) & 8191;
    float c = cospif((float)q * (1.0f / 4096.0f));
    float norm = (kk == 0) ? 0.022097086912079612f   // sqrt(1/2048)
                           : 0.03125f;                // sqrt(2/2048) = 1/32
    float v = c * norm;
    g_Dt[idx] = v;
    g_Et[idx] = v * g_bscale[kk];
}

// ---------------------------------------------------------------------------
// FP32 NT GEMM:  C[m][n] = sum_k A[m][k] * W[n][k]  (+ bias[n]) (optional relu)
// 128x128 block tile, BK=8, 256 threads, 8x8 per-thread tile, smem double buffer.
// Requires: M % 128 == 0, N % 128 == 0, K % 8 == 0 (all stages satisfy this).
// ---------------------------------------------------------------------------
__global__ __launch_bounds__(256)
void gemm_nt(const float* __restrict__ A, const float* __restrict__ W,
             const float* __restrict__ bias, float* __restrict__ C,
             int M, int N, int K, int do_relu)
{
    __shared__ float As[2][8][128];
    __shared__ float Ws[2][8][128];

    const int tid = threadIdx.x;
    const int bm  = blockIdx.y * 128;
    const int bn  = blockIdx.x * 128;

    // global-load mapping: 128 rows x 2 float4 column-groups
    const int lrow = tid >> 1;          // 0..127
    const int lcol = (tid & 1) << 2;    // 0 or 4

    const float* Ap = A + (size_t)(bm + lrow) * K + lcol;
    const float* Wp = W + (size_t)(bn + lrow) * K + lcol;

    // compute mapping: 16x16 thread grid, 8x8 output per thread
    const int tx = tid & 15;   // -> n
    const int ty = tid >> 4;   // -> m

    float acc[8][8];
    #pragma unroll
    for (int i = 0; i < 8; i++)
        #pragma unroll
        for (int j = 0; j < 8; j++) acc[i][j] = 0.0f;

    // prologue: tile 0
    {
        float4 a4 = *(const float4*)Ap;
        float4 w4 = *(const float4*)Wp;
        As[0][lcol + 0][lrow] = a4.x; As[0][lcol + 1][lrow] = a4.y;
        As[0][lcol + 2][lrow] = a4.z; As[0][lcol + 3][lrow] = a4.w;
        Ws[0][lcol + 0][lrow] = w4.x; Ws[0][lcol + 1][lrow] = w4.y;
        Ws[0][lcol + 2][lrow] = w4.z; Ws[0][lcol + 3][lrow] = w4.w;
    }
    __syncthreads();

    const int ktiles = K >> 3;
    int buf = 0;

    for (int kt = 0; kt < ktiles; kt++) {
        float4 na4, nw4;
        const bool has_next = (kt + 1 < ktiles);
        if (has_next) {
            na4 = *(const float4*)(Ap + (size_t)(kt + 1) * 8);
            nw4 = *(const float4*)(Wp + (size_t)(kt + 1) * 8);
        }

        #pragma unroll
        for (int kk = 0; kk < 8; kk++) {
            float af[8], wf[8];
            *(float4*)&af[0] = *(const float4*)&As[buf][kk][ty * 8];
            *(float4*)&af[4] = *(const float4*)&As[buf][kk][ty * 8 + 4];
            *(float4*)&wf[0] = *(const float4*)&Ws[buf][kk][tx * 8];
            *(float4*)&wf[4] = *(const float4*)&Ws[buf][kk][tx * 8 + 4];
            #pragma unroll
            for (int i = 0; i < 8; i++)
                #pragma unroll
                for (int j = 0; j < 8; j++)
                    acc[i][j] = fmaf(af[i], wf[j], acc[i][j]);
        }

        if (has_next) {
            const int nb = buf ^ 1;
            As[nb][lcol + 0][lrow] = na4.x; As[nb][lcol + 1][lrow] = na4.y;
            As[nb][lcol + 2][lrow] = na4.z; As[nb][lcol + 3][lrow] = na4.w;
            Ws[nb][lcol + 0][lrow] = nw4.x; Ws[nb][lcol + 1][lrow] = nw4.y;
            Ws[nb][lcol + 2][lrow] = nw4.z; Ws[nb][lcol + 3][lrow] = nw4.w;
            __syncthreads();
            buf = nb;
        }
    }

    // epilogue
    float bv[8];
    #pragma unroll
    for (int j = 0; j < 8; j++)
        bv[j] = bias ? bias[bn + tx * 8 + j] : 0.0f;

    #pragma unroll
    for (int i = 0; i < 8; i++) {
        float out[8];
        #pragma unroll
        for (int j = 0; j < 8; j++) {
            float v = acc[i][j] + bv[j];
            out[j] = do_relu ? fmaxf(v, 0.0f) : v;
        }
        size_t off = (size_t)(bm + ty * 8 + i) * N + bn + tx * 8;
        *(float4*)(C + off)     = *(const float4*)&out[0];
        *(float4*)(C + off + 4) = *(const float4*)&out[4];
    }
}

// ---------------------------------------------------------------------------
// Launch: fold DCT->scale->IDCT into Deff = D^T S D (symmetric), then fold
// Deff into W1:   mu/lv = MLP(relu(x @ (W1 Deff)^T + b1))
// ---------------------------------------------------------------------------
extern "C" void kernel_launch(void* const* d_in, const int* in_sizes, int n_in,
                              void* d_out, int out_size)
{
    const float* x   = (const float*)d_in[0];
    const float* fw  = (const float*)d_in[1];
    const float* kp  = (const float*)d_in[2];
    const float* W1  = (const float*)d_in[3];
    const float* b1  = (const float*)d_in[4];
    const float* W2  = (const float*)d_in[5];
    const float* b2  = (const float*)d_in[6];
    const float* Wmu = (const float*)d_in[7];
    const float* bmu = (const float*)d_in[8];
    const float* Wlv = (const float*)d_in[9];
    const float* blv = (const float*)d_in[10];
    float* out = (float*)d_out;

    float *Dt, *Et, *Deff, *W1e, *h1, *h2;
    cudaGetSymbolAddress((void**)&Dt,   g_Dt);
    cudaGetSymbolAddress((void**)&Et,   g_Et);
    cudaGetSymbolAddress((void**)&Deff, g_Deff);
    cudaGetSymbolAddress((void**)&W1e,  g_W1e);
    cudaGetSymbolAddress((void**)&h1,   g_h1);
    cudaGetSymbolAddress((void**)&h2,   g_h2);

    build_scale_kernel<<<8, 256>>>(fw, kp);
    build_D_kernel<<<(DIMN * DIMN) / 256, 256>>>();

    dim3 blk(256);

    // Deff[m][n] = sum_k Dt[m][k] * Et[n][k]      (2048,2048,2048)
    gemm_nt<<<dim3(16, 16), blk>>>(Dt, Et, nullptr, Deff, 2048, 2048, 2048, 0);

    // W1e[j][m] = sum_n W1[j][n] * Deff[m][n]  (= W1 @ Deff by symmetry)
    gemm_nt<<<dim3(16, 8), blk>>>(W1, Deff, nullptr, W1e, 1024, 2048, 2048, 0);

    // h1 = relu(x @ W1e^T + b1)                   (16384,1024,2048)
    gemm_nt<<<dim3(8, 128), blk>>>(x, W1e, b1, h1, BATCH, 1024, 2048, 1);

    // h2 = relu(h1 @ W2^T + b2)                   (16384,512,1024)
    gemm_nt<<<dim3(4, 128), blk>>>(h1, W2, b2, h2, BATCH, 512, 1024, 1);

    // mu = h2 @ Wmu^T + bmu                       (16384,256,512)
    gemm_nt<<<dim3(2, 128), blk>>>(h2, Wmu, bmu, out, BATCH, 256, 512, 0);

    // logvar = h2 @ Wlv^T + blv
    gemm_nt<<<dim3(2, 128), blk>>>(h2, Wlv, blv, out + (size_t)BATCH * 256,
                                   BATCH, 256, 512, 0);
}

// round 3
// speedup vs baseline: 2.6345x; 2.6345x over previous
#include <cuda_runtime.h>
#include <cuda_bf16.h>
#include <math.h>
#include <stdint.h>

// Problem constants
#define DIMN  2048
#define BATCH 16384

// ---------------------------------------------------------------------------
// Device scratch (static allocation — no runtime allocs allowed)
// ---------------------------------------------------------------------------
__device__ __align__(128) float g_Dt  [DIMN * DIMN];
__device__ __align__(128) float g_Et  [DIMN * DIMN];
__device__ __align__(128) float g_Deff[DIMN * DIMN];
__device__ __align__(128) float g_W1e [1024 * DIMN];
__device__ __align__(128) float g_h1  [BATCH * 1024];
__device__ __align__(128) float g_h2  [BATCH * 512];
__device__ float g_bscale[DIMN];

// ---------------------------------------------------------------------------
// Band-scale (verified in round 1)
// ---------------------------------------------------------------------------
__global__ void build_scale_kernel(const float* __restrict__ fw,
                                   const float* __restrict__ kptr)
{
    int idx = blockIdx.x * blockDim.x + threadIdx.x;
    if (idx >= DIMN) return;
    const float kv = *kptr;
    float val = 1.0f;
    const double step = 2047.0 / 30.0;
    #pragma unroll 1
    for (int i = 0; i < 30; i++) {
        int s = (int)(step * (double)i);
        int e = (i == 29) ? 2047 : (int)(step * (double)(i + 1));
        if (idx >= s && idx < e) {
            float f;
            if (e <= 30) f = 1.0f + fw[i] * kv * (1.0f - (float)i / 30.0f);
            else         f = 1.0f - fw[i] * kv * (1.0f - (float)(i - 30) / 30.0f);
            val = f;
        }
    }
    g_bscale[idx] = val;
}

// ---------------------------------------------------------------------------
// Build Dt/Et (verified in round 1; exact integer angle reduction + cospif)
// ---------------------------------------------------------------------------
__global__ void build_D_kernel()
{
    int idx = blockIdx.x * blockDim.x + threadIdx.x;
    int j  = idx >> 11;
    int kk = idx & (DIMN - 1);
    int q = ((2 * j + 1) * kk) & 8191;
    float c = cospif((float)q * (1.0f / 4096.0f));
    float norm = (kk == 0) ? 0.022097086912079612f : 0.03125f;
    float v = c * norm;
    g_Dt[idx] = v;
    g_Et[idx] = v * g_bscale[kk];
}

// ---------------------------------------------------------------------------
// mma.sync helpers (legacy tensor path — no sm_103a-gated instructions)
// ---------------------------------------------------------------------------
#define LDSM4(r0, r1, r2, r3, addr)                                            \
    asm volatile("ldmatrix.sync.aligned.m8n8.x4.shared.b16 {%0,%1,%2,%3}, [%4];" \
                 : "=r"(r0), "=r"(r1), "=r"(r2), "=r"(r3) : "r"(addr))

#define MMA16816(c, a, b)                                                      \
    asm volatile("mma.sync.aligned.m16n8k16.row.col.f32.bf16.bf16.f32 "        \
                 "{%0,%1,%2,%3},{%4,%5,%6,%7},{%8,%9},{%0,%1,%2,%3};"          \
                 : "+f"((c)[0]), "+f"((c)[1]), "+f"((c)[2]), "+f"((c)[3])      \
                 : "r"((a)[0]), "r"((a)[1]), "r"((a)[2]), "r"((a)[3]),         \
                   "r"((b)[0]), "r"((b)[1]))

#define STS128U(addr, a, b, c, d)                                              \
    asm volatile("st.shared.v4.b32 [%0], {%1,%2,%3,%4};"                       \
                 :: "r"(addr), "r"(a), "r"(b), "r"(c), "r"(d) : "memory")

static __device__ __forceinline__ uint32_t packbf(__nv_bfloat16 a, __nv_bfloat16 b)
{
    __nv_bfloat162 t(a, b);
    return *reinterpret_cast<uint32_t*>(&t);
}

// split two fp32 into packed bf16 hi pair + bf16 lo pair
static __device__ __forceinline__ void split2(float x, float y,
                                              uint32_t& hi, uint32_t& lo)
{
    __nv_bfloat16 hx = __float2bfloat16_rn(x);
    __nv_bfloat16 hy = __float2bfloat16_rn(y);
    float lx = x - __bfloat162float(hx);
    float ly = y - __bfloat162float(hy);
    hi = packbf(hx, hy);
    lo = packbf(__float2bfloat16_rn(lx), __float2bfloat16_rn(ly));
}

// ---------------------------------------------------------------------------
// bf16x3 NT GEMM on tensor cores: C[m][n] = sum_k A[m][k]*W[n][k] (+bias)(relu)
// 128x128 CTA tile, BK=32 (fp32), 2-stage smem double buffer.
// SMEM tiles: bf16, row stride 80B (pad) -> conflict-free ldmatrix.
// Warp grid 4(m) x 2(n); warp tile 32x64; accum fp32 in registers.
// Requires M%128==0, N%128==0, K%32==0.
// ---------------------------------------------------------------------------
#define ROWB        80u                      // padded row stride (bytes)
#define TILEB       (128u * ROWB)            // 10240 B per bf16 tile
#define STAGEB      (4u * TILEB)             // Ahi,Alo,Bhi,Blo
#define SMEM_GEMM   (2u * STAGEB)            // 81920 B

__global__ __launch_bounds__(256, 1)
void gemm_bf16x3(const float* __restrict__ A, const float* __restrict__ W,
                 const float* __restrict__ bias, float* __restrict__ C,
                 int M, int N, int K, int do_relu)
{
    extern __shared__ __align__(1024) char smem[];
    const uint32_t sb = (uint32_t)__cvta_generic_to_shared(smem);

    const int tid   = threadIdx.x;
    const int lane  = tid & 31;
    const int wid   = tid >> 5;
    const int warpm = wid & 3;            // 4 warps over M (32 rows each)
    const int warpn = wid >> 2;           // 2 warps over N (64 cols each)
    const int bm = blockIdx.y * 128;
    const int bn = blockIdx.x * 128;

    // global-load mapping: row = tid/2, 16-float half = tid&1
    const int lrow = tid >> 1;
    const int lcol = (tid & 1) << 4;
    const float* Ap = A + (size_t)(bm + lrow) * K + lcol;
    const float* Wp = W + (size_t)(bn + lrow) * K + lcol;
    const uint32_t stsOff = (uint32_t)lrow * ROWB + (uint32_t)(tid & 1) * 32u;

    // ldmatrix base offsets (lane-dependent)
    // A frag: rows warpm*32 + mf*16 + (lane&15), k-half (lane>>4)
    const uint32_t aRow = (uint32_t)(warpm * 32 + (lane & 15));
    const uint32_t aOff = aRow * ROWB + (uint32_t)(lane >> 4) * 16u;
    // B frag: n = warpn*64 + bf*16 + (lane&7) + ((lane&16)?8:0), k-half (lane>>3)&1
    const uint32_t bRow = (uint32_t)(warpn * 64 + (lane & 7) + ((lane & 16) ? 8 : 0));
    const uint32_t bOff = bRow * ROWB + (uint32_t)((lane >> 3) & 1) * 16u;

    float acc[2][8][4];
    #pragma unroll
    for (int i = 0; i < 2; i++)
        #pragma unroll
        for (int j = 0; j < 8; j++)
            #pragma unroll
            for (int q = 0; q < 4; q++) acc[i][j][q] = 0.0f;

    const int nk = K >> 5;

    // ---- prologue: stage 0 ----
    {
        const uint32_t aHi = sb,               aLo = sb + TILEB;
        const uint32_t bHi = sb + 2u * TILEB,  bLo = sb + 3u * TILEB;
        uint32_t h[8], l[8];
        #pragma unroll
        for (int f = 0; f < 4; f++) {
            float4 v = *(const float4*)(Ap + f * 4);
            split2(v.x, v.y, h[f * 2], l[f * 2]);
            split2(v.z, v.w, h[f * 2 + 1], l[f * 2 + 1]);
        }
        STS128U(aHi + stsOff,       h[0], h[1], h[2], h[3]);
        STS128U(aHi + stsOff + 16u, h[4], h[5], h[6], h[7]);
        STS128U(aLo + stsOff,       l[0], l[1], l[2], l[3]);
        STS128U(aLo + stsOff + 16u, l[4], l[5], l[6], l[7]);
        #pragma unroll
        for (int f = 0; f < 4; f++) {
            float4 v = *(const float4*)(Wp + f * 4);
            split2(v.x, v.y, h[f * 2], l[f * 2]);
            split2(v.z, v.w, h[f * 2 + 1], l[f * 2 + 1]);
        }
        STS128U(bHi + stsOff,       h[0], h[1], h[2], h[3]);
        STS128U(bHi + stsOff + 16u, h[4], h[5], h[6], h[7]);
        STS128U(bLo + stsOff,       l[0], l[1], l[2], l[3]);
        STS128U(bLo + stsOff + 16u, l[4], l[5], l[6], l[7]);
    }
    __syncthreads();

    for (int kt = 0; kt < nk; kt++) {
        const int buf = kt & 1;
        const uint32_t base = sb + (uint32_t)buf * STAGEB;
        const uint32_t aHi = base,              aLo = base + TILEB;
        const uint32_t bHi = base + 2u * TILEB, bLo = base + 3u * TILEB;

        // prefetch next stage into registers
        const bool has_next = (kt + 1 < nk);
        float4 av[4], wv[4];
        if (has_next) {
            const float* ap = Ap + (size_t)(kt + 1) * 32;
            const float* wp = Wp + (size_t)(kt + 1) * 32;
            #pragma unroll
            for (int f = 0; f < 4; f++) {
                av[f] = *(const float4*)(ap + f * 4);
                wv[f] = *(const float4*)(wp + f * 4);
            }
        }

        // compute: 2 k16-steps
        #pragma unroll
        for (int ks = 0; ks < 2; ks++) {
            const uint32_t kb = (uint32_t)ks * 32u;
            uint32_t Ah[2][4], Al[2][4], Bh[4][4], Bl[4][4];
            #pragma unroll
            for (int mf = 0; mf < 2; mf++) {
                uint32_t ad = aHi + aOff + (uint32_t)mf * (16u * ROWB) + kb;
                LDSM4(Ah[mf][0], Ah[mf][1], Ah[mf][2], Ah[mf][3], ad);
                uint32_t al = aLo + aOff + (uint32_t)mf * (16u * ROWB) + kb;
                LDSM4(Al[mf][0], Al[mf][1], Al[mf][2], Al[mf][3], al);
            }
            #pragma unroll
            for (int bf = 0; bf < 4; bf++) {
                uint32_t bd = bHi + bOff + (uint32_t)bf * (16u * ROWB) + kb;
                LDSM4(Bh[bf][0], Bh[bf][1], Bh[bf][2], Bh[bf][3], bd);
                uint32_t bl = bLo + bOff + (uint32_t)bf * (16u * ROWB) + kb;
                LDSM4(Bl[bf][0], Bl[bf][1], Bl[bf][2], Bl[bf][3], bl);
            }
            #pragma unroll
            for (int mf = 0; mf < 2; mf++) {
                #pragma unroll
                for (int nf = 0; nf < 8; nf++) {
                    uint32_t bh[2], bl2[2];
                    bh[0]  = Bh[nf >> 1][(nf & 1) ? 2 : 0];
                    bh[1]  = Bh[nf >> 1][(nf & 1) ? 3 : 1];
                    bl2[0] = Bl[nf >> 1][(nf & 1) ? 2 : 0];
                    bl2[1] = Bl[nf >> 1][(nf & 1) ? 3 : 1];
                    MMA16816(acc[mf][nf], Ah[mf], bh);   // hi*hi
                    MMA16816(acc[mf][nf], Ah[mf], bl2);  // hi*lo
                    MMA16816(acc[mf][nf], Al[mf], bh);   // lo*hi
                }
            }
        }

        // store next stage
        if (has_next) {
            const uint32_t nb = sb + (uint32_t)(buf ^ 1) * STAGEB;
            const uint32_t naHi = nb,              naLo = nb + TILEB;
            const uint32_t nbHi = nb + 2u * TILEB, nbLo = nb + 3u * TILEB;
            uint32_t h[8], l[8];
            #pragma unroll
            for (int f = 0; f < 4; f++) {
                split2(av[f].x, av[f].y, h[f * 2], l[f * 2]);
                split2(av[f].z, av[f].w, h[f * 2 + 1], l[f * 2 + 1]);
            }
            STS128U(naHi + stsOff,       h[0], h[1], h[2], h[3]);
            STS128U(naHi + stsOff + 16u, h[4], h[5], h[6], h[7]);
            STS128U(naLo + stsOff,       l[0], l[1], l[2], l[3]);
            STS128U(naLo + stsOff + 16u, l[4], l[5], l[6], l[7]);
            #pragma unroll
            for (int f = 0; f < 4; f++) {
                split2(wv[f].x, wv[f].y, h[f * 2], l[f * 2]);
                split2(wv[f].z, wv[f].w, h[f * 2 + 1], l[f * 2 + 1]);
            }
            STS128U(nbHi + stsOff,       h[0], h[1], h[2], h[3]);
            STS128U(nbHi + stsOff + 16u, h[4], h[5], h[6], h[7]);
            STS128U(nbLo + stsOff,       l[0], l[1], l[2], l[3]);
            STS128U(nbLo + stsOff + 16u, l[4], l[5], l[6], l[7]);
            __syncthreads();
        }
    }

    // ---- epilogue ----
    const int g  = lane >> 2;       // row within m16 frag
    const int tg = lane & 3;        // col pair within n8 frag
    #pragma unroll
    for (int mf = 0; mf < 2; mf++) {
        const int row0 = bm + warpm * 32 + mf * 16 + g;
        #pragma unroll
        for (int nf = 0; nf < 8; nf++) {
            const int col = bn + warpn * 64 + nf * 8 + tg * 2;
            float b0 = 0.0f, b1 = 0.0f;
            if (bias) { b0 = bias[col]; b1 = bias[col + 1]; }
            float v0 = acc[mf][nf][0] + b0;
            float v1 = acc[mf][nf][1] + b1;
            float v2 = acc[mf][nf][2] + b0;
            float v3 = acc[mf][nf][3] + b1;
            if (do_relu) {
                v0 = fmaxf(v0, 0.0f); v1 = fmaxf(v1, 0.0f);
                v2 = fmaxf(v2, 0.0f); v3 = fmaxf(v3, 0.0f);
            }
            float2 p0 = make_float2(v0, v1);
            float2 p1 = make_float2(v2, v3);
            *(float2*)(C + (size_t)row0 * N + col)       = p0;
            *(float2*)(C + (size_t)(row0 + 8) * N + col) = p1;
        }
    }
}

// ---------------------------------------------------------------------------
// Launch: Deff = D^T S D folded into W1, then tensorized MLP
// ---------------------------------------------------------------------------
extern "C" void kernel_launch(void* const* d_in, const int* in_sizes, int n_in,
                              void* d_out, int out_size)
{
    const float* x   = (const float*)d_in[0];
    const float* fw  = (const float*)d_in[1];
    const float* kp  = (const float*)d_in[2];
    const float* W1  = (const float*)d_in[3];
    const float* b1  = (const float*)d_in[4];
    const float* W2  = (const float*)d_in[5];
    const float* b2  = (const float*)d_in[6];
    const float* Wmu = (const float*)d_in[7];
    const float* bmu = (const float*)d_in[8];
    const float* Wlv = (const float*)d_in[9];
    const float* blv = (const float*)d_in[10];
    float* out = (float*)d_out;

    float *Dt, *Et, *Deff, *W1e, *h1, *h2;
    cudaGetSymbolAddress((void**)&Dt,   g_Dt);
    cudaGetSymbolAddress((void**)&Et,   g_Et);
    cudaGetSymbolAddress((void**)&Deff, g_Deff);
    cudaGetSymbolAddress((void**)&W1e,  g_W1e);
    cudaGetSymbolAddress((void**)&h1,   g_h1);
    cudaGetSymbolAddress((void**)&h2,   g_h2);

    cudaFuncSetAttribute(gemm_bf16x3,
                         cudaFuncAttributeMaxDynamicSharedMemorySize, SMEM_GEMM);

    build_scale_kernel<<<8, 256>>>(fw, kp);
    build_D_kernel<<<(DIMN * DIMN) / 256, 256>>>();

    // Deff[m][n] = sum_k Dt[m][k] * Et[n][k]
    gemm_bf16x3<<<dim3(16, 16), 256, SMEM_GEMM>>>(Dt, Et, nullptr, Deff,
                                                  2048, 2048, 2048, 0);
    // W1e = W1 @ Deff (Deff symmetric -> NT form)
    gemm_bf16x3<<<dim3(16, 8), 256, SMEM_GEMM>>>(W1, Deff, nullptr, W1e,
                                                 1024, 2048, 2048, 0);
    // h1 = relu(x @ W1e^T + b1)
    gemm_bf16x3<<<dim3(8, 128), 256, SMEM_GEMM>>>(x, W1e, b1, h1,
                                                  BATCH, 1024, 2048, 1);
    // h2 = relu(h1 @ W2^T + b2)
    gemm_bf16x3<<<dim3(4, 128), 256, SMEM_GEMM>>>(h1, W2, b2, h2,
                                                  BATCH, 512, 1024, 1);
    // mu
    gemm_bf16x3<<<dim3(2, 128), 256, SMEM_GEMM>>>(h2, Wmu, bmu, out,
                                                  BATCH, 256, 512, 0);
    // logvar
    gemm_bf16x3<<<dim3(2, 128), 256, SMEM_GEMM>>>(h2, Wlv, blv,
                                                  out + (size_t)BATCH * 256,
                                                  BATCH, 256, 512, 0);
}

// round 4
// speedup vs baseline: 2.7861x; 1.0576x over previous
#include <cuda_runtime.h>
#include <cuda_bf16.h>
#include <math.h>
#include <stdint.h>

// Problem constants
#define DIMN  2048
#define BATCH 16384

// GEMM tiling
#define BM    128
#define BN    128
#define BK    32
#define ROWB  80u                     // padded row stride (bytes) -> conflict-free LDSM
#define TILEB (128u * ROWB)           // 10240 B per bf16 tile
#define STAGEB (4u * TILEB)           // Ahi,Alo,Bhi,Blo = 40960 B
#define NST   4
#define SMEM_GEMM (NST * STAGEB)      // 163840 B

// ---------------------------------------------------------------------------
// Device scratch (static — no runtime allocs)
// ---------------------------------------------------------------------------
__device__ __align__(128) __nv_bfloat16 g_Dt_hi [DIMN * DIMN]; // Dt[m][k]=D[k][m]
__device__ __align__(128) __nv_bfloat16 g_Dt_lo [DIMN * DIMN];
__device__ __align__(128) __nv_bfloat16 g_Dm_hi [DIMN * DIMN]; // Dm[k][n]=D[k][n]
__device__ __align__(128) __nv_bfloat16 g_Dm_lo [DIMN * DIMN];
__device__ __align__(128) __nv_bfloat16 g_W1_hi [1024 * DIMN];
__device__ __align__(128) __nv_bfloat16 g_W1_lo [1024 * DIMN];
__device__ __align__(128) __nv_bfloat16 g_A1_hi [1024 * DIMN];
__device__ __align__(128) __nv_bfloat16 g_A1_lo [1024 * DIMN];
__device__ __align__(128) __nv_bfloat16 g_W1e_hi[1024 * DIMN];
__device__ __align__(128) __nv_bfloat16 g_W1e_lo[1024 * DIMN];
__device__ __align__(128) __nv_bfloat16 g_x_hi  [BATCH * DIMN];
__device__ __align__(128) __nv_bfloat16 g_x_lo  [BATCH * DIMN];
__device__ __align__(128) __nv_bfloat16 g_h1_hi [BATCH * 1024];
__device__ __align__(128) __nv_bfloat16 g_h1_lo [BATCH * 1024];
__device__ __align__(128) __nv_bfloat16 g_W2_hi [512 * 1024];
__device__ __align__(128) __nv_bfloat16 g_W2_lo [512 * 1024];
__device__ __align__(128) __nv_bfloat16 g_h2_hi [BATCH * 512];
__device__ __align__(128) __nv_bfloat16 g_h2_lo [BATCH * 512];
__device__ __align__(128) __nv_bfloat16 g_Wml_hi[512 * 512];
__device__ __align__(128) __nv_bfloat16 g_Wml_lo[512 * 512];
__device__ float g_bml[512];
__device__ float g_bscale[DIMN];

// ---------------------------------------------------------------------------
// Band-scale (verified round 1)
// ---------------------------------------------------------------------------
__global__ void build_scale_kernel(const float* __restrict__ fw,
                                   const float* __restrict__ kptr)
{
    int idx = blockIdx.x * blockDim.x + threadIdx.x;
    if (idx >= DIMN) return;
    const float kv = *kptr;
    float val = 1.0f;
    const double step = 2047.0 / 30.0;
    #pragma unroll 1
    for (int i = 0; i < 30; i++) {
        int s = (int)(step * (double)i);
        int e = (i == 29) ? 2047 : (int)(step * (double)(i + 1));
        if (idx >= s && idx < e) {
            float f;
            if (e <= 30) f = 1.0f + fw[i] * kv * (1.0f - (float)i / 30.0f);
            else         f = 1.0f - fw[i] * kv * (1.0f - (float)(i - 30) / 30.0f);
            val = f;
        }
    }
    g_bscale[idx] = val;
}

static __device__ __forceinline__ void bsplit(float v, __nv_bfloat16& h, __nv_bfloat16& l)
{
    h = __float2bfloat16_rn(v);
    l = __float2bfloat16_rn(v - __bfloat162float(h));
}

// ---------------------------------------------------------------------------
// Build Dt (D^T) and Dm (D) as bf16 hi/lo, both written coalesced.
// Exact integer angle reduction + cospif (verified round 1).
// ---------------------------------------------------------------------------
__global__ void build_D_kernel()
{
    int idx = blockIdx.x * blockDim.x + threadIdx.x;
    int r = idx >> 11;          // row
    int c = idx & (DIMN - 1);   // col
    const float n0 = 0.022097086912079612f;  // sqrt(1/2048)
    const float n1 = 0.03125f;               // sqrt(2/2048)

    // Dt[r][c] = D[c][r] = cos(pi*(r+0.5)*c/N) * s[c]
    int q1 = ((2 * r + 1) * c) & 8191;
    float v1 = cospif((float)q1 * (1.0f / 4096.0f)) * ((c == 0) ? n0 : n1);
    bsplit(v1, g_Dt_hi[idx], g_Dt_lo[idx]);

    // Dm[r][c] = D[r][c] = cos(pi*(c+0.5)*r/N) * s[r]
    int q2 = ((2 * c + 1) * r) & 8191;
    float v2 = cospif((float)q2 * (1.0f / 4096.0f)) * ((r == 0) ? n0 : n1);
    bsplit(v2, g_Dm_hi[idx], g_Dm_lo[idx]);
}

// ---------------------------------------------------------------------------
// fp32 -> bf16 hi/lo split conversion (vectorized, n % 4 == 0)
// ---------------------------------------------------------------------------
__global__ void convert_split(const float* __restrict__ s,
                              __nv_bfloat16* __restrict__ hi,
                              __nv_bfloat16* __restrict__ lo, int n)
{
    int i = (blockIdx.x * blockDim.x + threadIdx.x) << 2;
    if (i >= n) return;
    float4 v = *(const float4*)(s + i);
    __nv_bfloat16 h0, h1, h2, h3, l0, l1, l2, l3;
    bsplit(v.x, h0, l0); bsplit(v.y, h1, l1);
    bsplit(v.z, h2, l2); bsplit(v.w, h3, l3);
    __nv_bfloat162 hp0(h0, h1), hp1(h2, h3), lp0(l0, l1), lp1(l2, l3);
    *(__nv_bfloat162*)(hi + i)     = hp0;
    *(__nv_bfloat162*)(hi + i + 2) = hp1;
    *(__nv_bfloat162*)(lo + i)     = lp0;
    *(__nv_bfloat162*)(lo + i + 2) = lp1;
}

__global__ void merge_bias(const float* __restrict__ bmu, const float* __restrict__ blv)
{
    int i = blockIdx.x * blockDim.x + threadIdx.x;
    if (i < 256)      g_bml[i] = bmu[i];
    else if (i < 512) g_bml[i] = blv[i - 256];
}

// ---------------------------------------------------------------------------
// mma.sync / ldmatrix / cp.async helpers
// ---------------------------------------------------------------------------
#define LDSM4(r0, r1, r2, r3, addr)                                            \
    asm volatile("ldmatrix.sync.aligned.m8n8.x4.shared.b16 {%0,%1,%2,%3}, [%4];" \
                 : "=r"(r0), "=r"(r1), "=r"(r2), "=r"(r3) : "r"(addr))

#define MMA16816(c, a, b)                                                      \
    asm volatile("mma.sync.aligned.m16n8k16.row.col.f32.bf16.bf16.f32 "        \
                 "{%0,%1,%2,%3},{%4,%5,%6,%7},{%8,%9},{%0,%1,%2,%3};"          \
                 : "+f"((c)[0]), "+f"((c)[1]), "+f"((c)[2]), "+f"((c)[3])      \
                 : "r"((a)[0]), "r"((a)[1]), "r"((a)[2]), "r"((a)[3]),         \
                   "r"((b)[0]), "r"((b)[1]))

#define CP16(sa, ga)                                                           \
    asm volatile("cp.async.cg.shared.global [%0], [%1], 16;"                   \
                 :: "r"(sa), "l"(ga) : "memory")
#define CP_COMMIT() asm volatile("cp.async.commit_group;" ::: "memory")
#define CP_WAIT()   asm volatile("cp.async.wait_group %0;" :: "n"(NST - 2) : "memory")

static __device__ __forceinline__ uint32_t packbf(__nv_bfloat16 a, __nv_bfloat16 b)
{
    __nv_bfloat162 t(a, b);
    return *reinterpret_cast<uint32_t*>(&t);
}

// ---------------------------------------------------------------------------
// bf16x3 tensor-core NT GEMM, cp.async 4-stage pipeline.
// C[m][n] = sum_k A[m][k]*B[n][k], A/B pre-split bf16 hi/lo.
// Epilogue: optional colscale, bias, relu; output either split bf16 hi/lo
// (Ch/Cl) or fp32 final (Cf, mu/logvar interleaved mapping, N==512).
// Requires M%128==0, N%128==0, K%32==0, nk >= NST.
// ---------------------------------------------------------------------------
__global__ __launch_bounds__(256, 1)
void gemm_bf16x3(const __nv_bfloat16* __restrict__ Ahp,
                 const __nv_bfloat16* __restrict__ Alp,
                 const __nv_bfloat16* __restrict__ Bhp,
                 const __nv_bfloat16* __restrict__ Blp,
                 const float* __restrict__ bias,
                 const float* __restrict__ colscale,
                 __nv_bfloat16* __restrict__ Ch,
                 __nv_bfloat16* __restrict__ Cl,
                 float* __restrict__ Cf,
                 int M, int N, int K, int do_relu)
{
    extern __shared__ __align__(1024) char smem[];
    const uint32_t sb = (uint32_t)__cvta_generic_to_shared(smem);

    const int tid   = threadIdx.x;
    const int lane  = tid & 31;
    const int wid   = tid >> 5;
    const int warpm = wid & 3;
    const int warpn = wid >> 2;
    const int bm = blockIdx.y * BM;
    const int bn = blockIdx.x * BN;

    // ldmatrix lane offsets (verified round 3)
    const uint32_t aRow = (uint32_t)(warpm * 32 + (lane & 15));
    const uint32_t aOff = aRow * ROWB + (uint32_t)(lane >> 4) * 16u;
    const uint32_t bRow = (uint32_t)(warpn * 64 + (lane & 7) + ((lane & 16) ? 8 : 0));
    const uint32_t bOff = bRow * ROWB + (uint32_t)((lane >> 3) & 1) * 16u;

    float acc[2][8][4];
    #pragma unroll
    for (int i = 0; i < 2; i++)
        #pragma unroll
        for (int j = 0; j < 8; j++)
            #pragma unroll
            for (int q = 0; q < 4; q++) acc[i][j][q] = 0.0f;

    const int nk = K >> 5;

    // cp.async stage issue: 512 16B-chunks per tile, 2 per thread per tile
    auto issue_stage = [&](int kt) {
        const uint32_t base = sb + (uint32_t)(kt & (NST - 1)) * STAGEB;
        const size_t kof = (size_t)kt * BK;
        #pragma unroll
        for (int h = 0; h < 2; h++) {
            const int c   = tid + h * 256;
            const int row = c >> 2;
            const int q   = c & 3;
            const uint32_t so = (uint32_t)row * ROWB + (uint32_t)q * 16u;
            const size_t ga = (size_t)(bm + row) * K + kof + (size_t)q * 8;
            const size_t gb = (size_t)(bn + row) * K + kof + (size_t)q * 8;
            CP16(base + so,               Ahp + ga);
            CP16(base + TILEB + so,       Alp + ga);
            CP16(base + 2u * TILEB + so,  Bhp + gb);
            CP16(base + 3u * TILEB + so,  Blp + gb);
        }
    };

    // prologue: NST-1 stages in flight
    #pragma unroll
    for (int s = 0; s < NST - 1; s++) { issue_stage(s); CP_COMMIT(); }

    for (int kt = 0; kt < nk; kt++) {
        CP_WAIT();
        __syncthreads();                 // stage kt ready; prev compute done

        if (kt + NST - 1 < nk) issue_stage(kt + NST - 1);
        CP_COMMIT();                     // (possibly empty) keeps group count

        const uint32_t base = sb + (uint32_t)(kt & (NST - 1)) * STAGEB;
        const uint32_t aHi = base,              aLo = base + TILEB;
        const uint32_t bHi = base + 2u * TILEB, bLo = base + 3u * TILEB;

        #pragma unroll
        for (int ks = 0; ks < 2; ks++) {
            const uint32_t kb = (uint32_t)ks * 32u;
            uint32_t Ah[2][4], Al[2][4], Bh[4][4], Bl[4][4];
            #pragma unroll
            for (int mf = 0; mf < 2; mf++) {
                uint32_t ad = aHi + aOff + (uint32_t)mf * (16u * ROWB) + kb;
                LDSM4(Ah[mf][0], Ah[mf][1], Ah[mf][2], Ah[mf][3], ad);
                uint32_t al = aLo + aOff + (uint32_t)mf * (16u * ROWB) + kb;
                LDSM4(Al[mf][0], Al[mf][1], Al[mf][2], Al[mf][3], al);
            }
            #pragma unroll
            for (int bf = 0; bf < 4; bf++) {
                uint32_t bd = bHi + bOff + (uint32_t)bf * (16u * ROWB) + kb;
                LDSM4(Bh[bf][0], Bh[bf][1], Bh[bf][2], Bh[bf][3], bd);
                uint32_t bl = bLo + bOff + (uint32_t)bf * (16u * ROWB) + kb;
                LDSM4(Bl[bf][0], Bl[bf][1], Bl[bf][2], Bl[bf][3], bl);
            }
            #pragma unroll
            for (int mf = 0; mf < 2; mf++) {
                #pragma unroll
                for (int nf = 0; nf < 8; nf++) {
                    uint32_t bh[2], bl2[2];
                    bh[0]  = Bh[nf >> 1][(nf & 1) ? 2 : 0];
                    bh[1]  = Bh[nf >> 1][(nf & 1) ? 3 : 1];
                    bl2[0] = Bl[nf >> 1][(nf & 1) ? 2 : 0];
                    bl2[1] = Bl[nf >> 1][(nf & 1) ? 3 : 1];
                    MMA16816(acc[mf][nf], Ah[mf], bh);   // hi*hi
                    MMA16816(acc[mf][nf], Ah[mf], bl2);  // hi*lo
                    MMA16816(acc[mf][nf], Al[mf], bh);   // lo*hi
                }
            }
        }
    }

    // ---- epilogue ----
    const int g  = lane >> 2;
    const int tg = lane & 3;
    #pragma unroll
    for (int mf = 0; mf < 2; mf++) {
        const int r0 = bm + warpm * 32 + mf * 16 + g;
        #pragma unroll
        for (int nf = 0; nf < 8; nf++) {
            const int col = bn + warpn * 64 + nf * 8 + tg * 2;
            float v0 = acc[mf][nf][0], v1 = acc[mf][nf][1];
            float v2 = acc[mf][nf][2], v3 = acc[mf][nf][3];
            if (colscale) {
                float s0 = colscale[col], s1 = colscale[col + 1];
                v0 *= s0; v1 *= s1; v2 *= s0; v3 *= s1;
            }
            if (bias) {
                float b0 = bias[col], b1 = bias[col + 1];
                v0 += b0; v1 += b1; v2 += b0; v3 += b1;
            }
            if (do_relu) {
                v0 = fmaxf(v0, 0.0f); v1 = fmaxf(v1, 0.0f);
                v2 = fmaxf(v2, 0.0f); v3 = fmaxf(v3, 0.0f);
            }
            if (Cf) {
                // final: N==512; cols [0,256) -> mu, [256,512) -> logvar
                float* p0;
                float* p1;
                if (col < 256) {
                    p0 = Cf + (size_t)r0 * 256 + col;
                    p1 = Cf + (size_t)(r0 + 8) * 256 + col;
                } else {
                    float* half2 = Cf + (size_t)BATCH * 256;
                    p0 = half2 + (size_t)r0 * 256 + (col - 256);
                    p1 = half2 + (size_t)(r0 + 8) * 256 + (col - 256);
                }
                *(float2*)p0 = make_float2(v0, v1);
                *(float2*)p1 = make_float2(v2, v3);
            } else {
                __nv_bfloat16 h0, h1, h2, h3, l0, l1, l2, l3;
                bsplit(v0, h0, l0); bsplit(v1, h1, l1);
                bsplit(v2, h2, l2); bsplit(v3, h3, l3);
                *(uint32_t*)(Ch + (size_t)r0 * N + col)       = packbf(h0, h1);
                *(uint32_t*)(Cl + (size_t)r0 * N + col)       = packbf(l0, l1);
                *(uint32_t*)(Ch + (size_t)(r0 + 8) * N + col) = packbf(h2, h3);
                *(uint32_t*)(Cl + (size_t)(r0 + 8) * N + col) = packbf(l2, l3);
            }
        }
    }
}

// ---------------------------------------------------------------------------
// Launch: W1e = ((W1 D^T) diag(s)) D  folded weight, then split-bf16 MLP
// ---------------------------------------------------------------------------
extern "C" void kernel_launch(void* const* d_in, const int* in_sizes, int n_in,
                              void* d_out, int out_size)
{
    const float* x   = (const float*)d_in[0];
    const float* fw  = (const float*)d_in[1];
    const float* kp  = (const float*)d_in[2];
    const float* W1  = (const float*)d_in[3];
    const float* b1  = (const float*)d_in[4];
    const float* W2  = (const float*)d_in[5];
    const float* b2  = (const float*)d_in[6];
    const float* Wmu = (const float*)d_in[7];
    const float* bmu = (const float*)d_in[8];
    const float* Wlv = (const float*)d_in[9];
    const float* blv = (const float*)d_in[10];
    float* out = (float*)d_out;

    __nv_bfloat16 *Dt_h, *Dt_l, *Dm_h, *Dm_l, *W1_h, *W1_l, *A1_h, *A1_l;
    __nv_bfloat16 *W1e_h, *W1e_l, *x_h, *x_l, *h1_h, *h1_l;
    __nv_bfloat16 *W2_h, *W2_l, *h2_h, *h2_l, *Wml_h, *Wml_l;
    float *bml, *bscale;
    cudaGetSymbolAddress((void**)&Dt_h,  g_Dt_hi);  cudaGetSymbolAddress((void**)&Dt_l,  g_Dt_lo);
    cudaGetSymbolAddress((void**)&Dm_h,  g_Dm_hi);  cudaGetSymbolAddress((void**)&Dm_l,  g_Dm_lo);
    cudaGetSymbolAddress((void**)&W1_h,  g_W1_hi);  cudaGetSymbolAddress((void**)&W1_l,  g_W1_lo);
    cudaGetSymbolAddress((void**)&A1_h,  g_A1_hi);  cudaGetSymbolAddress((void**)&A1_l,  g_A1_lo);
    cudaGetSymbolAddress((void**)&W1e_h, g_W1e_hi); cudaGetSymbolAddress((void**)&W1e_l, g_W1e_lo);
    cudaGetSymbolAddress((void**)&x_h,   g_x_hi);   cudaGetSymbolAddress((void**)&x_l,   g_x_lo);
    cudaGetSymbolAddress((void**)&h1_h,  g_h1_hi);  cudaGetSymbolAddress((void**)&h1_l,  g_h1_lo);
    cudaGetSymbolAddress((void**)&W2_h,  g_W2_hi);  cudaGetSymbolAddress((void**)&W2_l,  g_W2_lo);
    cudaGetSymbolAddress((void**)&h2_h,  g_h2_hi);  cudaGetSymbolAddress((void**)&h2_l,  g_h2_lo);
    cudaGetSymbolAddress((void**)&Wml_h, g_Wml_hi); cudaGetSymbolAddress((void**)&Wml_l, g_Wml_lo);
    cudaGetSymbolAddress((void**)&bml,   g_bml);
    cudaGetSymbolAddress((void**)&bscale, g_bscale);

    cudaFuncSetAttribute(gemm_bf16x3,
                         cudaFuncAttributeMaxDynamicSharedMemorySize, SMEM_GEMM);

    build_scale_kernel<<<8, 256>>>(fw, kp);
    build_D_kernel<<<(DIMN * DIMN) / 256, 256>>>();

    convert_split<<<(BATCH * DIMN / 4 + 255) / 256, 256>>>(x, x_h, x_l, BATCH * DIMN);
    convert_split<<<(1024 * DIMN / 4 + 255) / 256, 256>>>(W1, W1_h, W1_l, 1024 * DIMN);
    convert_split<<<(512 * 1024 / 4 + 255) / 256, 256>>>(W2, W2_h, W2_l, 512 * 1024);
    convert_split<<<(256 * 512 / 4 + 255) / 256, 256>>>(Wmu, Wml_h, Wml_l, 256 * 512);
    convert_split<<<(256 * 512 / 4 + 255) / 256, 256>>>(Wlv, Wml_h + 256 * 512,
                                                        Wml_l + 256 * 512, 256 * 512);
    merge_bias<<<2, 256>>>(bmu, blv);

    // A1[j][kf] = sum_n W1[j][n] * D[kf][n], scaled by bscale[kf] in epilogue
    gemm_bf16x3<<<dim3(16, 8), 256, SMEM_GEMM>>>(
        W1_h, W1_l, Dm_h, Dm_l, nullptr, bscale, A1_h, A1_l, nullptr,
        1024, 2048, 2048, 0);
    // W1e[j][m] = sum_kf A1[j][kf] * Dt[m][kf]
    gemm_bf16x3<<<dim3(16, 8), 256, SMEM_GEMM>>>(
        A1_h, A1_l, Dt_h, Dt_l, nullptr, nullptr, W1e_h, W1e_l, nullptr,
        1024, 2048, 2048, 0);
    // h1 = relu(x @ W1e^T + b1)
    gemm_bf16x3<<<dim3(8, 128), 256, SMEM_GEMM>>>(
        x_h, x_l, W1e_h, W1e_l, b1, nullptr, h1_h, h1_l, nullptr,
        BATCH, 1024, 2048, 1);
    // h2 = relu(h1 @ W2^T + b2)
    gemm_bf16x3<<<dim3(4, 128), 256, SMEM_GEMM>>>(
        h1_h, h1_l, W2_h, W2_l, b2, nullptr, h2_h, h2_l, nullptr,
        BATCH, 512, 1024, 1);
    // [mu | logvar] = h2 @ [Wmu;Wlv]^T + [bmu;blv]  (final fp32, split mapping)
    gemm_bf16x3<<<dim3(4, 128), 256, SMEM_GEMM>>>(
        h2_h, h2_l, Wml_h, Wml_l, bml, nullptr, nullptr, nullptr, out,
        BATCH, 512, 512, 0);
}

// round 5
// speedup vs baseline: 3.0750x; 1.1037x over previous
#include <cuda_runtime.h>
#include <cuda_bf16.h>
#include <math.h>
#include <stdint.h>

// Problem constants
#define DIMN  2048
#define BATCH 16384

// GEMM tiling
#define BM    128
#define BN    128
#define BK    64
#define ROWB  144u                    // 128B data + 16B pad -> conflict-free LDSM
#define TILEB (128u * ROWB)           // 18432 B per bf16 tile
#define STAGEB (4u * TILEB)           // Ahi,Alo,Bhi,Blo = 73728 B
#define NST   3
#define SMEM_GEMM (NST * STAGEB)      // 221184 B

// ---------------------------------------------------------------------------
// Device scratch (static — no runtime allocs)
// ---------------------------------------------------------------------------
__device__ __align__(128) __nv_bfloat16 g_Dt_hi [DIMN * DIMN];
__device__ __align__(128) __nv_bfloat16 g_Dt_lo [DIMN * DIMN];
__device__ __align__(128) __nv_bfloat16 g_Dm_hi [DIMN * DIMN];
__device__ __align__(128) __nv_bfloat16 g_Dm_lo [DIMN * DIMN];
__device__ __align__(128) __nv_bfloat16 g_W1_hi [1024 * DIMN];
__device__ __align__(128) __nv_bfloat16 g_W1_lo [1024 * DIMN];
__device__ __align__(128) __nv_bfloat16 g_A1_hi [1024 * DIMN];
__device__ __align__(128) __nv_bfloat16 g_A1_lo [1024 * DIMN];
__device__ __align__(128) __nv_bfloat16 g_W1e_hi[1024 * DIMN];
__device__ __align__(128) __nv_bfloat16 g_W1e_lo[1024 * DIMN];
__device__ __align__(128) __nv_bfloat16 g_x_hi  [BATCH * DIMN];
__device__ __align__(128) __nv_bfloat16 g_x_lo  [BATCH * DIMN];
__device__ __align__(128) __nv_bfloat16 g_h1_hi [BATCH * 1024];
__device__ __align__(128) __nv_bfloat16 g_h1_lo [BATCH * 1024];
__device__ __align__(128) __nv_bfloat16 g_W2_hi [512 * 1024];
__device__ __align__(128) __nv_bfloat16 g_W2_lo [512 * 1024];
__device__ __align__(128) __nv_bfloat16 g_h2_hi [BATCH * 512];
__device__ __align__(128) __nv_bfloat16 g_h2_lo [BATCH * 512];
__device__ __align__(128) __nv_bfloat16 g_Wml_hi[512 * 512];
__device__ __align__(128) __nv_bfloat16 g_Wml_lo[512 * 512];
__device__ __align__(128) float g_part[4 * 1024 * DIMN];   // split-K partials
__device__ float g_bml[512];
__device__ float g_bscale[DIMN];

// ---------------------------------------------------------------------------
// Band-scale (verified round 1)
// ---------------------------------------------------------------------------
__global__ void build_scale_kernel(const float* __restrict__ fw,
                                   const float* __restrict__ kptr)
{
    int idx = blockIdx.x * blockDim.x + threadIdx.x;
    if (idx >= DIMN) return;
    const float kv = *kptr;
    float val = 1.0f;
    const double step = 2047.0 / 30.0;
    #pragma unroll 1
    for (int i = 0; i < 30; i++) {
        int s = (int)(step * (double)i);
        int e = (i == 29) ? 2047 : (int)(step * (double)(i + 1));
        if (idx >= s && idx < e) {
            float f;
            if (e <= 30) f = 1.0f + fw[i] * kv * (1.0f - (float)i / 30.0f);
            else         f = 1.0f - fw[i] * kv * (1.0f - (float)(i - 30) / 30.0f);
            val = f;
        }
    }
    g_bscale[idx] = val;
}

static __device__ __forceinline__ void bsplit(float v, __nv_bfloat16& h, __nv_bfloat16& l)
{
    h = __float2bfloat16_rn(v);
    l = __float2bfloat16_rn(v - __bfloat162float(h));
}

// ---------------------------------------------------------------------------
// Build Dt (D^T) and Dm (D) as bf16 hi/lo (verified round 4)
// ---------------------------------------------------------------------------
__global__ void build_D_kernel()
{
    int idx = blockIdx.x * blockDim.x + threadIdx.x;
    int r = idx >> 11;
    int c = idx & (DIMN - 1);
    const float n0 = 0.022097086912079612f;  // sqrt(1/2048)
    const float n1 = 0.03125f;               // sqrt(2/2048)

    int q1 = ((2 * r + 1) * c) & 8191;
    float v1 = cospif((float)q1 * (1.0f / 4096.0f)) * ((c == 0) ? n0 : n1);
    bsplit(v1, g_Dt_hi[idx], g_Dt_lo[idx]);

    int q2 = ((2 * c + 1) * r) & 8191;
    float v2 = cospif((float)q2 * (1.0f / 4096.0f)) * ((r == 0) ? n0 : n1);
    bsplit(v2, g_Dm_hi[idx], g_Dm_lo[idx]);
}

// ---------------------------------------------------------------------------
// fp32 -> bf16 hi/lo split conversion (vectorized, n % 4 == 0)
// ---------------------------------------------------------------------------
__global__ void convert_split(const float* __restrict__ s,
                              __nv_bfloat16* __restrict__ hi,
                              __nv_bfloat16* __restrict__ lo, int n)
{
    int i = (blockIdx.x * blockDim.x + threadIdx.x) << 2;
    if (i >= n) return;
    float4 v = *(const float4*)(s + i);
    __nv_bfloat16 h0, h1, h2, h3, l0, l1, l2, l3;
    bsplit(v.x, h0, l0); bsplit(v.y, h1, l1);
    bsplit(v.z, h2, l2); bsplit(v.w, h3, l3);
    __nv_bfloat162 hp0(h0, h1), hp1(h2, h3), lp0(l0, l1), lp1(l2, l3);
    *(__nv_bfloat162*)(hi + i)     = hp0;
    *(__nv_bfloat162*)(hi + i + 2) = hp1;
    *(__nv_bfloat162*)(lo + i)     = lp0;
    *(__nv_bfloat162*)(lo + i + 2) = lp1;
}

// sum 4 split-K fp32 partials -> (optional colscale) -> bf16 hi/lo
// N must be a power of two.
__global__ void reduce4_split(const float* __restrict__ part,
                              const float* __restrict__ colscale,
                              __nv_bfloat16* __restrict__ hi,
                              __nv_bfloat16* __restrict__ lo,
                              int n, int N)
{
    int i = (blockIdx.x * blockDim.x + threadIdx.x) << 2;
    if (i >= n) return;
    float4 a = *(const float4*)(part + i);
    float4 b = *(const float4*)(part + (size_t)n + i);
    float4 c = *(const float4*)(part + 2 * (size_t)n + i);
    float4 d = *(const float4*)(part + 3 * (size_t)n + i);
    float v0 = (a.x + b.x) + (c.x + d.x);
    float v1 = (a.y + b.y) + (c.y + d.y);
    float v2 = (a.z + b.z) + (c.z + d.z);
    float v3 = (a.w + b.w) + (c.w + d.w);
    if (colscale) {
        int col = i & (N - 1);
        v0 *= colscale[col];     v1 *= colscale[col + 1];
        v2 *= colscale[col + 2]; v3 *= colscale[col + 3];
    }
    __nv_bfloat16 h0, h1, h2, h3, l0, l1, l2, l3;
    bsplit(v0, h0, l0); bsplit(v1, h1, l1);
    bsplit(v2, h2, l2); bsplit(v3, h3, l3);
    __nv_bfloat162 hp0(h0, h1), hp1(h2, h3), lp0(l0, l1), lp1(l2, l3);
    *(__nv_bfloat162*)(hi + i)     = hp0;
    *(__nv_bfloat162*)(hi + i + 2) = hp1;
    *(__nv_bfloat162*)(lo + i)     = lp0;
    *(__nv_bfloat162*)(lo + i + 2) = lp1;
}

__global__ void merge_bias(const float* __restrict__ bmu, const float* __restrict__ blv)
{
    int i = blockIdx.x * blockDim.x + threadIdx.x;
    if (i < 256)      g_bml[i] = bmu[i];
    else if (i < 512) g_bml[i] = blv[i - 256];
}

// ---------------------------------------------------------------------------
// mma.sync / ldmatrix / cp.async helpers
// ---------------------------------------------------------------------------
#define LDSM4(r0, r1, r2, r3, addr)                                            \
    asm volatile("ldmatrix.sync.aligned.m8n8.x4.shared.b16 {%0,%1,%2,%3}, [%4];" \
                 : "=r"(r0), "=r"(r1), "=r"(r2), "=r"(r3) : "r"(addr))

#define MMA16816(c, a, b)                                                      \
    asm volatile("mma.sync.aligned.m16n8k16.row.col.f32.bf16.bf16.f32 "        \
                 "{%0,%1,%2,%3},{%4,%5,%6,%7},{%8,%9},{%0,%1,%2,%3};"          \
                 : "+f"((c)[0]), "+f"((c)[1]), "+f"((c)[2]), "+f"((c)[3])      \
                 : "r"((a)[0]), "r"((a)[1]), "r"((a)[2]), "r"((a)[3]),         \
                   "r"((b)[0]), "r"((b)[1]))

#define CP16(sa, ga)                                                           \
    asm volatile("cp.async.cg.shared.global [%0], [%1], 16;"                   \
                 :: "r"(sa), "l"(ga) : "memory")
#define CP_COMMIT() asm volatile("cp.async.commit_group;" ::: "memory")
#define CP_WAIT()   asm volatile("cp.async.wait_group %0;" :: "n"(NST - 2) : "memory")

static __device__ __forceinline__ uint32_t packbf(__nv_bfloat16 a, __nv_bfloat16 b)
{
    __nv_bfloat162 t(a, b);
    return *reinterpret_cast<uint32_t*>(&t);
}

// ---------------------------------------------------------------------------
// bf16x3 tensor-core NT GEMM, cp.async 3-stage pipeline, BK=64.
// C[m][n] = sum_k A[m][k]*B[n][k] over klen columns starting at
// kbase = blockIdx.z * klen (split-K via grid z).
// Output modes: Cpart (fp32 split-K partial, plane blockIdx.z)
//               Cf    (fp32 final, mu/logvar mapping, N==512)
//               Ch/Cl (bf16 hi/lo split, +colscale/bias/relu)
// Requires M%128==0, N%128==0, klen%64==0, klen/64 >= NST.
// ---------------------------------------------------------------------------
__global__ __launch_bounds__(256, 1)
void gemm_bf16x3(const __nv_bfloat16* __restrict__ Ahp,
                 const __nv_bfloat16* __restrict__ Alp,
                 const __nv_bfloat16* __restrict__ Bhp,
                 const __nv_bfloat16* __restrict__ Blp,
                 const float* __restrict__ bias,
                 const float* __restrict__ colscale,
                 __nv_bfloat16* __restrict__ Ch,
                 __nv_bfloat16* __restrict__ Cl,
                 float* __restrict__ Cf,
                 float* __restrict__ Cpart,
                 int M, int N, int K, int klen, int do_relu)
{
    extern __shared__ __align__(1024) char smem[];
    const uint32_t sb = (uint32_t)__cvta_generic_to_shared(smem);

    const int tid   = threadIdx.x;
    const int lane  = tid & 31;
    const int wid   = tid >> 5;
    const int warpm = wid & 3;
    const int warpn = wid >> 2;
    const int bm = blockIdx.y * BM;
    const int bn = blockIdx.x * BN;
    const int kbase = blockIdx.z * klen;

    const uint32_t aOff = (uint32_t)(warpm * 32 + (lane & 15)) * ROWB
                        + (uint32_t)(lane >> 4) * 16u;
    const uint32_t bOff = (uint32_t)(warpn * 64 + (lane & 7) + ((lane & 16) ? 8 : 0)) * ROWB
                        + (uint32_t)((lane >> 3) & 1) * 16u;

    float acc[2][8][4];
    #pragma unroll
    for (int i = 0; i < 2; i++)
        #pragma unroll
        for (int j = 0; j < 8; j++)
            #pragma unroll
            for (int q = 0; q < 4; q++) acc[i][j][q] = 0.0f;

    const int nk = klen >> 6;

    // 1024 16B chunks per tile, 4 tiles; 16 cp.async per thread per stage
    auto issue_stage = [&](int kt) {
        const uint32_t base = sb + (uint32_t)(kt % NST) * STAGEB;
        const size_t kof = (size_t)kbase + (size_t)kt * BK;
        #pragma unroll
        for (int h = 0; h < 4; h++) {
            const int c   = tid + h * 256;
            const int row = c >> 3;
            const int q   = c & 7;
            const uint32_t so = (uint32_t)row * ROWB + (uint32_t)q * 16u;
            const size_t ga = (size_t)(bm + row) * K + kof + (size_t)q * 8;
            const size_t gb = (size_t)(bn + row) * K + kof + (size_t)q * 8;
            CP16(base + so,               Ahp + ga);
            CP16(base + TILEB + so,       Alp + ga);
            CP16(base + 2u * TILEB + so,  Bhp + gb);
            CP16(base + 3u * TILEB + so,  Blp + gb);
        }
    };

    #pragma unroll
    for (int s = 0; s < NST - 1; s++) { issue_stage(s); CP_COMMIT(); }

    for (int kt = 0; kt < nk; kt++) {
        CP_WAIT();
        __syncthreads();

        if (kt + NST - 1 < nk) issue_stage(kt + NST - 1);
        CP_COMMIT();

        const uint32_t base = sb + (uint32_t)(kt % NST) * STAGEB;
        const uint32_t aHi = base,              aLo = base + TILEB;
        const uint32_t bHi = base + 2u * TILEB, bLo = base + 3u * TILEB;

        #pragma unroll
        for (int ks = 0; ks < 4; ks++) {
            const uint32_t kb = (uint32_t)ks * 32u;
            uint32_t Ah[2][4], Al[2][4], Bh[4][4], Bl[4][4];
            #pragma unroll
            for (int mf = 0; mf < 2; mf++) {
                uint32_t ad = aHi + aOff + (uint32_t)mf * (16u * ROWB) + kb;
                LDSM4(Ah[mf][0], Ah[mf][1], Ah[mf][2], Ah[mf][3], ad);
                uint32_t al = aLo + aOff + (uint32_t)mf * (16u * ROWB) + kb;
                LDSM4(Al[mf][0], Al[mf][1], Al[mf][2], Al[mf][3], al);
            }
            #pragma unroll
            for (int bf = 0; bf < 4; bf++) {
                uint32_t bd = bHi + bOff + (uint32_t)bf * (16u * ROWB) + kb;
                LDSM4(Bh[bf][0], Bh[bf][1], Bh[bf][2], Bh[bf][3], bd);
                uint32_t bl = bLo + bOff + (uint32_t)bf * (16u * ROWB) + kb;
                LDSM4(Bl[bf][0], Bl[bf][1], Bl[bf][2], Bl[bf][3], bl);
            }
            #pragma unroll
            for (int mf = 0; mf < 2; mf++) {
                #pragma unroll
                for (int nf = 0; nf < 8; nf++) {
                    uint32_t bh[2], bl2[2];
                    bh[0]  = Bh[nf >> 1][(nf & 1) ? 2 : 0];
                    bh[1]  = Bh[nf >> 1][(nf & 1) ? 3 : 1];
                    bl2[0] = Bl[nf >> 1][(nf & 1) ? 2 : 0];
                    bl2[1] = Bl[nf >> 1][(nf & 1) ? 3 : 1];
                    MMA16816(acc[mf][nf], Ah[mf], bh);   // hi*hi
                    MMA16816(acc[mf][nf], Ah[mf], bl2);  // hi*lo
                    MMA16816(acc[mf][nf], Al[mf], bh);   // lo*hi
                }
            }
        }
    }

    // ---- epilogue ----
    const int g  = lane >> 2;
    const int tg = lane & 3;
    #pragma unroll
    for (int mf = 0; mf < 2; mf++) {
        const int r0 = bm + warpm * 32 + mf * 16 + g;
        #pragma unroll
        for (int nf = 0; nf < 8; nf++) {
            const int col = bn + warpn * 64 + nf * 8 + tg * 2;
            float v0 = acc[mf][nf][0], v1 = acc[mf][nf][1];
            float v2 = acc[mf][nf][2], v3 = acc[mf][nf][3];

            if (Cpart) {   // split-K fp32 partial, plane = blockIdx.z
                float* base2 = Cpart + (size_t)blockIdx.z * ((size_t)M * N);
                *(float2*)(base2 + (size_t)r0 * N + col)       = make_float2(v0, v1);
                *(float2*)(base2 + (size_t)(r0 + 8) * N + col) = make_float2(v2, v3);
                continue;
            }
            if (colscale) {
                float s0 = colscale[col], s1 = colscale[col + 1];
                v0 *= s0; v1 *= s1; v2 *= s0; v3 *= s1;
            }
            if (bias) {
                float b0 = bias[col], b1 = bias[col + 1];
                v0 += b0; v1 += b1; v2 += b0; v3 += b1;
            }
            if (do_relu) {
                v0 = fmaxf(v0, 0.0f); v1 = fmaxf(v1, 0.0f);
                v2 = fmaxf(v2, 0.0f); v3 = fmaxf(v3, 0.0f);
            }
            if (Cf) {      // final: N==512; cols [0,256) mu, [256,512) logvar
                float* p0;
                float* p1;
                if (col < 256) {
                    p0 = Cf + (size_t)r0 * 256 + col;
                    p1 = Cf + (size_t)(r0 + 8) * 256 + col;
                } else {
                    float* half2 = Cf + (size_t)BATCH * 256;
                    p0 = half2 + (size_t)r0 * 256 + (col - 256);
                    p1 = half2 + (size_t)(r0 + 8) * 256 + (col - 256);
                }
                *(float2*)p0 = make_float2(v0, v1);
                *(float2*)p1 = make_float2(v2, v3);
            } else {
                __nv_bfloat16 h0, h1, h2, h3, l0, l1, l2, l3;
                bsplit(v0, h0, l0); bsplit(v1, h1, l1);
                bsplit(v2, h2, l2); bsplit(v3, h3, l3);
                *(uint32_t*)(Ch + (size_t)r0 * N + col)       = packbf(h0, h1);
                *(uint32_t*)(Cl + (size_t)r0 * N + col)       = packbf(l0, l1);
                *(uint32_t*)(Ch + (size_t)(r0 + 8) * N + col) = packbf(h2, h3);
                *(uint32_t*)(Cl + (size_t)(r0 + 8) * N + col) = packbf(l2, l3);
            }
        }
    }
}

// ---------------------------------------------------------------------------
// Launch: W1e = ((W1 D^T) diag(s)) D folded weight (split-K), then MLP
// ---------------------------------------------------------------------------
extern "C" void kernel_launch(void* const* d_in, const int* in_sizes, int n_in,
                              void* d_out, int out_size)
{
    const float* x   = (const float*)d_in[0];
    const float* fw  = (const float*)d_in[1];
    const float* kp  = (const float*)d_in[2];
    const float* W1  = (const float*)d_in[3];
    const float* b1  = (const float*)d_in[4];
    const float* W2  = (const float*)d_in[5];
    const float* b2  = (const float*)d_in[6];
    const float* Wmu = (const float*)d_in[7];
    const float* bmu = (const float*)d_in[8];
    const float* Wlv = (const float*)d_in[9];
    const float* blv = (const float*)d_in[10];
    float* out = (float*)d_out;

    __nv_bfloat16 *Dt_h, *Dt_l, *Dm_h, *Dm_l, *W1_h, *W1_l, *A1_h, *A1_l;
    __nv_bfloat16 *W1e_h, *W1e_l, *x_h, *x_l, *h1_h, *h1_l;
    __nv_bfloat16 *W2_h, *W2_l, *h2_h, *h2_l, *Wml_h, *Wml_l;
    float *bml, *bscale, *part;
    cudaGetSymbolAddress((void**)&Dt_h,  g_Dt_hi);  cudaGetSymbolAddress((void**)&Dt_l,  g_Dt_lo);
    cudaGetSymbolAddress((void**)&Dm_h,  g_Dm_hi);  cudaGetSymbolAddress((void**)&Dm_l,  g_Dm_lo);
    cudaGetSymbolAddress((void**)&W1_h,  g_W1_hi);  cudaGetSymbolAddress((void**)&W1_l,  g_W1_lo);
    cudaGetSymbolAddress((void**)&A1_h,  g_A1_hi);  cudaGetSymbolAddress((void**)&A1_l,  g_A1_lo);
    cudaGetSymbolAddress((void**)&W1e_h, g_W1e_hi); cudaGetSymbolAddress((void**)&W1e_l, g_W1e_lo);
    cudaGetSymbolAddress((void**)&x_h,   g_x_hi);   cudaGetSymbolAddress((void**)&x_l,   g_x_lo);
    cudaGetSymbolAddress((void**)&h1_h,  g_h1_hi);  cudaGetSymbolAddress((void**)&h1_l,  g_h1_lo);
    cudaGetSymbolAddress((void**)&W2_h,  g_W2_hi);  cudaGetSymbolAddress((void**)&W2_l,  g_W2_lo);
    cudaGetSymbolAddress((void**)&h2_h,  g_h2_hi);  cudaGetSymbolAddress((void**)&h2_l,  g_h2_lo);
    cudaGetSymbolAddress((void**)&Wml_h, g_Wml_hi); cudaGetSymbolAddress((void**)&Wml_l, g_Wml_lo);
    cudaGetSymbolAddress((void**)&bml,   g_bml);
    cudaGetSymbolAddress((void**)&bscale, g_bscale);
    cudaGetSymbolAddress((void**)&part,  g_part);

    cudaFuncSetAttribute(gemm_bf16x3,
                         cudaFuncAttributeMaxDynamicSharedMemorySize, SMEM_GEMM);

    build_scale_kernel<<<8, 256>>>(fw, kp);
    build_D_kernel<<<(DIMN * DIMN) / 256, 256>>>();

    convert_split<<<(BATCH * DIMN / 4 + 255) / 256, 256>>>(x, x_h, x_l, BATCH * DIMN);
    convert_split<<<(1024 * DIMN / 4 + 255) / 256, 256>>>(W1, W1_h, W1_l, 1024 * DIMN);
    convert_split<<<(512 * 1024 / 4 + 255) / 256, 256>>>(W2, W2_h, W2_l, 512 * 1024);
    convert_split<<<(256 * 512 / 4 + 255) / 256, 256>>>(Wmu, Wml_h, Wml_l, 256 * 512);
    convert_split<<<(256 * 512 / 4 + 255) / 256, 256>>>(Wlv, Wml_h + 256 * 512,
                                                        Wml_l + 256 * 512, 256 * 512);
    merge_bias<<<2, 256>>>(bmu, blv);

    const int nW = 1024 * DIMN;       // weight-GEMM output elems

    // A1[j][kf] = (sum_n W1[j][n] * D[kf][n]) * bscale[kf]   (split-K=4)
    gemm_bf16x3<<<dim3(16, 8, 4), 256, SMEM_GEMM>>>(
        W1_h, W1_l, Dm_h, Dm_l, nullptr, nullptr, nullptr, nullptr, nullptr,
        part, 1024, 2048, 2048, 512, 0);
    reduce4_split<<<(nW / 4 + 255) / 256, 256>>>(part, bscale, A1_h, A1_l, nW, 2048);

    // W1e[j][m] = sum_kf A1[j][kf] * Dt[m][kf]               (split-K=4)
    gemm_bf16x3<<<dim3(16, 8, 4), 256, SMEM_GEMM>>>(
        A1_h, A1_l, Dt_h, Dt_l, nullptr, nullptr, nullptr, nullptr, nullptr,
        part, 1024, 2048, 2048, 512, 0);
    reduce4_split<<<(nW / 4 + 255) / 256, 256>>>(part, nullptr, W1e_h, W1e_l, nW, 2048);

    // h1 = relu(x @ W1e^T + b1)
    gemm_bf16x3<<<dim3(8, 128, 1), 256, SMEM_GEMM>>>(
        x_h, x_l, W1e_h, W1e_l, b1, nullptr, h1_h, h1_l, nullptr, nullptr,
        BATCH, 1024, 2048, 2048, 1);
    // h2 = relu(h1 @ W2^T + b2)
    gemm_bf16x3<<<dim3(4, 128, 1), 256, SMEM_GEMM>>>(
        h1_h, h1_l, W2_h, W2_l, b2, nullptr, h2_h, h2_l, nullptr, nullptr,
        BATCH, 512, 1024, 1024, 1);
    // [mu | logvar] = h2 @ [Wmu;Wlv]^T + [bmu;blv]
    gemm_bf16x3<<<dim3(4, 128, 1), 256, SMEM_GEMM>>>(
        h2_h, h2_l, Wml_h, Wml_l, bml, nullptr, nullptr, nullptr, out, nullptr,
        BATCH, 512, 512, 512, 0);
}

// round 7
// speedup vs baseline: 3.1213x; 1.0151x over previous
#include <cuda_runtime.h>
#include <cuda_bf16.h>
#include <math.h>
#include <stdint.h>

// Problem constants
#define DIMN  2048
#define BATCH 16384

// GEMM tiling
#define BM    128
#define BN    128
#define BK    64
#define ROWB  144u                    // 128B data + 16B pad -> conflict-free LDSM
#define TILEB (128u * ROWB)           // 18432 B per bf16 tile
#define STAGEB (4u * TILEB)           // Ahi,Alo,Bhi,Blo = 73728 B
#define NST   3
#define SMEM_GEMM (NST * STAGEB)      // 221184 B

// ---------------------------------------------------------------------------
// Device scratch (static — no runtime allocs)
// ---------------------------------------------------------------------------
__device__ __align__(128) __nv_bfloat16 g_Dt_hi [DIMN * DIMN];
__device__ __align__(128) __nv_bfloat16 g_Dt_lo [DIMN * DIMN];
__device__ __align__(128) __nv_bfloat16 g_Dm_hi [DIMN * DIMN];
__device__ __align__(128) __nv_bfloat16 g_Dm_lo [DIMN * DIMN];
__device__ __align__(128) __nv_bfloat16 g_W1_hi [1024 * DIMN];
__device__ __align__(128) __nv_bfloat16 g_W1_lo [1024 * DIMN];
__device__ __align__(128) __nv_bfloat16 g_A1_hi [1024 * DIMN];
__device__ __align__(128) __nv_bfloat16 g_A1_lo [1024 * DIMN];
__device__ __align__(128) __nv_bfloat16 g_W1e_hi[1024 * DIMN];
__device__ __align__(128) __nv_bfloat16 g_W1e_lo[1024 * DIMN];
__device__ __align__(128) __nv_bfloat16 g_x_hi  [BATCH * DIMN];
__device__ __align__(128) __nv_bfloat16 g_x_lo  [BATCH * DIMN];
__device__ __align__(128) __nv_bfloat16 g_h1_hi [BATCH * 1024];
__device__ __align__(128) __nv_bfloat16 g_h1_lo [BATCH * 1024];
__device__ __align__(128) __nv_bfloat16 g_W2_hi [512 * 1024];
__device__ __align__(128) __nv_bfloat16 g_W2_lo [512 * 1024];
__device__ __align__(128) __nv_bfloat16 g_h2_hi [BATCH * 512];
__device__ __align__(128) __nv_bfloat16 g_h2_lo [BATCH * 512];
__device__ __align__(128) __nv_bfloat16 g_Wml_hi[512 * 512];
__device__ __align__(128) __nv_bfloat16 g_Wml_lo[512 * 512];
__device__ __align__(128) float g_part[4 * 1024 * DIMN];   // split-K partials
__device__ float g_bml[512];
__device__ float g_bscale[DIMN];

// ---------------------------------------------------------------------------
// Band-scale (verified round 1)
// ---------------------------------------------------------------------------
__global__ void build_scale_kernel(const float* __restrict__ fw,
                                   const float* __restrict__ kptr)
{
    int idx = blockIdx.x * blockDim.x + threadIdx.x;
    if (idx >= DIMN) return;
    const float kv = *kptr;
    float val = 1.0f;
    const double step = 2047.0 / 30.0;
    #pragma unroll 1
    for (int i = 0; i < 30; i++) {
        int s = (int)(step * (double)i);
        int e = (i == 29) ? 2047 : (int)(step * (double)(i + 1));
        if (idx >= s && idx < e) {
            float f;
            if (e <= 30) f = 1.0f + fw[i] * kv * (1.0f - (float)i / 30.0f);
            else         f = 1.0f - fw[i] * kv * (1.0f - (float)(i - 30) / 30.0f);
            val = f;
        }
    }
    g_bscale[idx] = val;
}

static __device__ __forceinline__ void bsplit(float v, __nv_bfloat16& h, __nv_bfloat16& l)
{
    h = __float2bfloat16_rn(v);
    l = __float2bfloat16_rn(v - __bfloat162float(h));
}

static __device__ __forceinline__ uint32_t packbf(__nv_bfloat16 a, __nv_bfloat16 b)
{
    __nv_bfloat162 t(a, b);
    return *reinterpret_cast<uint32_t*>(&t);
}

// ---------------------------------------------------------------------------
// Build Dt (D^T) and Dm (D) as bf16 hi/lo (verified round 4)
// ---------------------------------------------------------------------------
__global__ void build_D_kernel()
{
    int idx = blockIdx.x * blockDim.x + threadIdx.x;
    int r = idx >> 11;
    int c = idx & (DIMN - 1);
    const float n0 = 0.022097086912079612f;  // sqrt(1/2048)
    const float n1 = 0.03125f;               // sqrt(2/2048)

    int q1 = ((2 * r + 1) * c) & 8191;
    float v1 = cospif((float)q1 * (1.0f / 4096.0f)) * ((c == 0) ? n0 : n1);
    bsplit(v1, g_Dt_hi[idx], g_Dt_lo[idx]);

    int q2 = ((2 * c + 1) * r) & 8191;
    float v2 = cospif((float)q2 * (1.0f / 4096.0f)) * ((r == 0) ? n0 : n1);
    bsplit(v2, g_Dm_hi[idx], g_Dm_lo[idx]);
}

// ---------------------------------------------------------------------------
// fp32 -> bf16 hi/lo split, 8 elems/thread, 16B hi/lo stores (n % 8 == 0)
// ---------------------------------------------------------------------------
__global__ void convert_split(const float* __restrict__ s,
                              __nv_bfloat16* __restrict__ hi,
                              __nv_bfloat16* __restrict__ lo, int n)
{
    int i = (blockIdx.x * blockDim.x + threadIdx.x) << 3;
    if (i >= n) return;
    float4 v0 = *(const float4*)(s + i);
    float4 v1 = *(const float4*)(s + i + 4);
    __nv_bfloat16 h0, h1, h2, h3, h4, h5, h6, h7;
    __nv_bfloat16 l0, l1, l2, l3, l4, l5, l6, l7;
    bsplit(v0.x, h0, l0); bsplit(v0.y, h1, l1);
    bsplit(v0.z, h2, l2); bsplit(v0.w, h3, l3);
    bsplit(v1.x, h4, l4); bsplit(v1.y, h5, l5);
    bsplit(v1.z, h6, l6); bsplit(v1.w, h7, l7);
    uint4 hbuf, lbuf;
    hbuf.x = packbf(h0, h1); hbuf.y = packbf(h2, h3);
    hbuf.z = packbf(h4, h5); hbuf.w = packbf(h6, h7);
    lbuf.x = packbf(l0, l1); lbuf.y = packbf(l2, l3);
    lbuf.z = packbf(l4, l5); lbuf.w = packbf(l6, l7);
    *(uint4*)(hi + i) = hbuf;
    *(uint4*)(lo + i) = lbuf;
}

// sum 4 split-K fp32 partials -> (optional colscale) -> bf16 hi/lo
// N must be a power of two.
__global__ void reduce4_split(const float* __restrict__ part,
                              const float* __restrict__ colscale,
                              __nv_bfloat16* __restrict__ hi,
                              __nv_bfloat16* __restrict__ lo,
                              int n, int N)
{
    int i = (blockIdx.x * blockDim.x + threadIdx.x) << 2;
    if (i >= n) return;
    float4 a = *(const float4*)(part + i);
    float4 b = *(const float4*)(part + (size_t)n + i);
    float4 c = *(const float4*)(part + 2 * (size_t)n + i);
    float4 d = *(const float4*)(part + 3 * (size_t)n + i);
    float v0 = (a.x + b.x) + (c.x + d.x);
    float v1 = (a.y + b.y) + (c.y + d.y);
    float v2 = (a.z + b.z) + (c.z + d.z);
    float v3 = (a.w + b.w) + (c.w + d.w);
    if (colscale) {
        int col = i & (N - 1);
        v0 *= colscale[col];     v1 *= colscale[col + 1];
        v2 *= colscale[col + 2]; v3 *= colscale[col + 3];
    }
    __nv_bfloat16 h0, h1, h2, h3, l0, l1, l2, l3;
    bsplit(v0, h0, l0); bsplit(v1, h1, l1);
    bsplit(v2, h2, l2); bsplit(v3, h3, l3);
    __nv_bfloat162 hp0(h0, h1), hp1(h2, h3), lp0(l0, l1), lp1(l2, l3);
    *(__nv_bfloat162*)(hi + i)     = hp0;
    *(__nv_bfloat162*)(hi + i + 2) = hp1;
    *(__nv_bfloat162*)(lo + i)     = lp0;
    *(__nv_bfloat162*)(lo + i + 2) = lp1;
}

__global__ void merge_bias(const float* __restrict__ bmu, const float* __restrict__ blv)
{
    int i = blockIdx.x * blockDim.x + threadIdx.x;
    if (i < 256)      g_bml[i] = bmu[i];
    else if (i < 512) g_bml[i] = blv[i - 256];
}

// ---------------------------------------------------------------------------
// mma.sync / ldmatrix / cp.async helpers
// ---------------------------------------------------------------------------
#define LDSM4(r0, r1, r2, r3, addr)                                            \
    asm volatile("ldmatrix.sync.aligned.m8n8.x4.shared.b16 {%0,%1,%2,%3}, [%4];" \
                 : "=r"(r0), "=r"(r1), "=r"(r2), "=r"(r3) : "r"(addr))

#define MMA16816(c, a, b)                                                      \
    asm volatile("mma.sync.aligned.m16n8k16.row.col.f32.bf16.bf16.f32 "        \
                 "{%0,%1,%2,%3},{%4,%5,%6,%7},{%8,%9},{%0,%1,%2,%3};"          \
                 : "+f"((c)[0]), "+f"((c)[1]), "+f"((c)[2]), "+f"((c)[3])      \
                 : "r"((a)[0]), "r"((a)[1]), "r"((a)[2]), "r"((a)[3]),         \
                   "r"((b)[0]), "r"((b)[1]))

#define CP16(sa, ga)                                                           \
    asm volatile("cp.async.cg.shared.global [%0], [%1], 16;"                   \
                 :: "r"(sa), "l"(ga) : "memory")
#define CP_COMMIT() asm volatile("cp.async.commit_group;" ::: "memory")
#define CP_WAIT()   asm volatile("cp.async.wait_group %0;" :: "n"(NST - 2) : "memory")

// Fragment register block: [0..7]=Ah, [8..15]=Al, [16..31]=Bh, [32..47]=Bl
#define F_AH(F, mf) (&(F)[(mf) * 4])
#define F_AL(F, mf) (&(F)[8 + (mf) * 4])
#define F_BH(F, bf) (&(F)[16 + (bf) * 4])
#define F_BL(F, bf) (&(F)[32 + (bf) * 4])

// ---------------------------------------------------------------------------
// bf16x3 tensor-core NT GEMM, cp.async 3-stage pipeline, BK=64,
// register double-buffered fragments across the 4 k16-steps per tile.
// ---------------------------------------------------------------------------
__global__ __launch_bounds__(256, 1)
void gemm_bf16x3(const __nv_bfloat16* __restrict__ Ahp,
                 const __nv_bfloat16* __restrict__ Alp,
                 const __nv_bfloat16* __restrict__ Bhp,
                 const __nv_bfloat16* __restrict__ Blp,
                 const float* __restrict__ bias,
                 const float* __restrict__ colscale,
                 __nv_bfloat16* __restrict__ Ch,
                 __nv_bfloat16* __restrict__ Cl,
                 float* __restrict__ Cf,
                 float* __restrict__ Cpart,
                 int M, int N, int K, int klen, int do_relu)
{
    extern __shared__ __align__(1024) char smem[];
    const uint32_t sb = (uint32_t)__cvta_generic_to_shared(smem);

    const int tid   = threadIdx.x;
    const int lane  = tid & 31;
    const int wid   = tid >> 5;
    const int warpm = wid & 3;
    const int warpn = wid >> 2;
    const int bm = blockIdx.y * BM;
    const int bn = blockIdx.x * BN;
    const int kbase = blockIdx.z * klen;

    const uint32_t aOff = (uint32_t)(warpm * 32 + (lane & 15)) * ROWB
                        + (uint32_t)(lane >> 4) * 16u;
    const uint32_t bOff = (uint32_t)(warpn * 64 + (lane & 7) + ((lane & 16) ? 8 : 0)) * ROWB
                        + (uint32_t)((lane >> 3) & 1) * 16u;

    float acc[2][8][4];
    #pragma unroll
    for (int i = 0; i < 2; i++)
        #pragma unroll
        for (int j = 0; j < 8; j++)
            #pragma unroll
            for (int q = 0; q < 4; q++) acc[i][j][q] = 0.0f;

    const int nk = klen >> 6;

    auto issue_stage = [&](int kt) {
        const uint32_t base = sb + (uint32_t)(kt % NST) * STAGEB;
        const size_t kof = (size_t)kbase + (size_t)kt * BK;
        #pragma unroll
        for (int h = 0; h < 4; h++) {
            const int c   = tid + h * 256;
            const int row = c >> 3;
            const int q   = c & 7;
            const uint32_t so = (uint32_t)row * ROWB + (uint32_t)q * 16u;
            const size_t ga = (size_t)(bm + row) * K + kof + (size_t)q * 8;
            const size_t gb = (size_t)(bn + row) * K + kof + (size_t)q * 8;
            CP16(base + so,               Ahp + ga);
            CP16(base + TILEB + so,       Alp + ga);
            CP16(base + 2u * TILEB + so,  Bhp + gb);
            CP16(base + 3u * TILEB + so,  Blp + gb);
        }
    };

    auto load_frags = [&](uint32_t base, uint32_t kb, uint32_t* F) {
        const uint32_t aHi = base,              aLo = base + TILEB;
        const uint32_t bHi = base + 2u * TILEB, bLo = base + 3u * TILEB;
        #pragma unroll
        for (int mf = 0; mf < 2; mf++) {
            uint32_t ad = aHi + aOff + (uint32_t)mf * (16u * ROWB) + kb;
            LDSM4(F[mf*4+0], F[mf*4+1], F[mf*4+2], F[mf*4+3], ad);
            uint32_t al = aLo + aOff + (uint32_t)mf * (16u * ROWB) + kb;
            LDSM4(F[8+mf*4+0], F[8+mf*4+1], F[8+mf*4+2], F[8+mf*4+3], al);
        }
        #pragma unroll
        for (int bf = 0; bf < 4; bf++) {
            uint32_t bd = bHi + bOff + (uint32_t)bf * (16u * ROWB) + kb;
            LDSM4(F[16+bf*4+0], F[16+bf*4+1], F[16+bf*4+2], F[16+bf*4+3], bd);
            uint32_t bl = bLo + bOff + (uint32_t)bf * (16u * ROWB) + kb;
            LDSM4(F[32+bf*4+0], F[32+bf*4+1], F[32+bf*4+2], F[32+bf*4+3], bl);
        }
    };

    auto mma_step = [&](const uint32_t* F) {
        #pragma unroll
        for (int mf = 0; mf < 2; mf++) {
            #pragma unroll
            for (int nf = 0; nf < 8; nf++) {
                const uint32_t* BhF = F_BH(F, nf >> 1);
                const uint32_t* BlF = F_BL(F, nf >> 1);
                uint32_t bh[2], bl2[2];
                bh[0]  = BhF[(nf & 1) ? 2 : 0];
                bh[1]  = BhF[(nf & 1) ? 3 : 1];
                bl2[0] = BlF[(nf & 1) ? 2 : 0];
                bl2[1] = BlF[(nf & 1) ? 3 : 1];
                MMA16816(acc[mf][nf], F_AH(F, mf), bh);   // hi*hi
                MMA16816(acc[mf][nf], F_AH(F, mf), bl2);  // hi*lo
                MMA16816(acc[mf][nf], F_AL(F, mf), bh);   // lo*hi
            }
        }
    };

    #pragma unroll
    for (int s = 0; s < NST - 1; s++) { issue_stage(s); CP_COMMIT(); }

    uint32_t Fr[2][48];

    for (int kt = 0; kt < nk; kt++) {
        CP_WAIT();
        __syncthreads();

        const uint32_t base = sb + (uint32_t)(kt % NST) * STAGEB;

        load_frags(base, 0u, Fr[0]);          // ks=0 fragments

        if (kt + NST - 1 < nk) issue_stage(kt + NST - 1);
        CP_COMMIT();

        #pragma unroll
        for (int ks = 0; ks < 4; ks++) {
            if (ks < 3)
                load_frags(base, (uint32_t)(ks + 1) * 32u, Fr[(ks + 1) & 1]);
            mma_step(Fr[ks & 1]);
        }
    }

    // ---- epilogue ----
    const int g  = lane >> 2;
    const int tg = lane & 3;
    #pragma unroll
    for (int mf = 0; mf < 2; mf++) {
        const int r0 = bm + warpm * 32 + mf * 16 + g;
        #pragma unroll
        for (int nf = 0; nf < 8; nf++) {
            const int col = bn + warpn * 64 + nf * 8 + tg * 2;
            float v0 = acc[mf][nf][0], v1 = acc[mf][nf][1];
            float v2 = acc[mf][nf][2], v3 = acc[mf][nf][3];

            if (Cpart) {
                float* base2 = Cpart + (size_t)blockIdx.z * ((size_t)M * N);
                *(float2*)(base2 + (size_t)r0 * N + col)       = make_float2(v0, v1);
                *(float2*)(base2 + (size_t)(r0 + 8) * N + col) = make_float2(v2, v3);
                continue;
            }
            if (colscale) {
                float s0 = colscale[col], s1 = colscale[col + 1];
                v0 *= s0; v1 *= s1; v2 *= s0; v3 *= s1;
            }
            if (bias) {
                float b0 = bias[col], b1 = bias[col + 1];
                v0 += b0; v1 += b1; v2 += b0; v3 += b1;
            }
            if (do_relu) {
                v0 = fmaxf(v0, 0.0f); v1 = fmaxf(v1, 0.0f);
                v2 = fmaxf(v2, 0.0f); v3 = fmaxf(v3, 0.0f);
            }
            if (Cf) {      // final: N==512; cols [0,256) mu, [256,512) logvar
                float* p0;
                float* p1;
                if (col < 256) {
                    p0 = Cf + (size_t)r0 * 256 + col;
                    p1 = Cf + (size_t)(r0 + 8) * 256 + col;
                } else {
                    float* half2 = Cf + (size_t)BATCH * 256;
                    p0 = half2 + (size_t)r0 * 256 + (col - 256);
                    p1 = half2 + (size_t)(r0 + 8) * 256 + (col - 256);
                }
                *(float2*)p0 = make_float2(v0, v1);
                *(float2*)p1 = make_float2(v2, v3);
            } else {
                __nv_bfloat16 h0, h1, h2, h3, l0, l1, l2, l3;
                bsplit(v0, h0, l0); bsplit(v1, h1, l1);
                bsplit(v2, h2, l2); bsplit(v3, h3, l3);
                *(uint32_t*)(Ch + (size_t)r0 * N + col)       = packbf(h0, h1);
                *(uint32_t*)(Cl + (size_t)r0 * N + col)       = packbf(l0, l1);
                *(uint32_t*)(Ch + (size_t)(r0 + 8) * N + col) = packbf(h2, h3);
                *(uint32_t*)(Cl + (size_t)(r0 + 8) * N + col) = packbf(l2, l3);
            }
        }
    }
}

// ---------------------------------------------------------------------------
// Launch
// ---------------------------------------------------------------------------
extern "C" void kernel_launch(void* const* d_in, const int* in_sizes, int n_in,
                              void* d_out, int out_size)
{
    const float* x   = (const float*)d_in[0];
    const float* fw  = (const float*)d_in[1];
    const float* kp  = (const float*)d_in[2];
    const float* W1  = (const float*)d_in[3];
    const float* b1  = (const float*)d_in[4];
    const float* W2  = (const float*)d_in[5];
    const float* b2  = (const float*)d_in[6];
    const float* Wmu = (const float*)d_in[7];
    const float* bmu = (const float*)d_in[8];
    const float* Wlv = (const float*)d_in[9];
    const float* blv = (const float*)d_in[10];
    float* out = (float*)d_out;

    __nv_bfloat16 *Dt_h, *Dt_l, *Dm_h, *Dm_l, *W1_h, *W1_l, *A1_h, *A1_l;
    __nv_bfloat16 *W1e_h, *W1e_l, *x_h, *x_l, *h1_h, *h1_l;
    __nv_bfloat16 *W2_h, *W2_l, *h2_h, *h2_l, *Wml_h, *Wml_l;
    float *bml, *bscale, *part;
    cudaGetSymbolAddress((void**)&Dt_h,  g_Dt_hi);  cudaGetSymbolAddress((void**)&Dt_l,  g_Dt_lo);
    cudaGetSymbolAddress((void**)&Dm_h,  g_Dm_hi);  cudaGetSymbolAddress((void**)&Dm_l,  g_Dm_lo);
    cudaGetSymbolAddress((void**)&W1_h,  g_W1_hi);  cudaGetSymbolAddress((void**)&W1_l,  g_W1_lo);
    cudaGetSymbolAddress((void**)&A1_h,  g_A1_hi);  cudaGetSymbolAddress((void**)&A1_l,  g_A1_lo);
    cudaGetSymbolAddress((void**)&W1e_h, g_W1e_hi); cudaGetSymbolAddress((void**)&W1e_l, g_W1e_lo);
    cudaGetSymbolAddress((void**)&x_h,   g_x_hi);   cudaGetSymbolAddress((void**)&x_l,   g_x_lo);
    cudaGetSymbolAddress((void**)&h1_h,  g_h1_hi);  cudaGetSymbolAddress((void**)&h1_l,  g_h1_lo);
    cudaGetSymbolAddress((void**)&W2_h,  g_W2_hi);  cudaGetSymbolAddress((void**)&W2_l,  g_W2_lo);
    cudaGetSymbolAddress((void**)&h2_h,  g_h2_hi);  cudaGetSymbolAddress((void**)&h2_l,  g_h2_lo);
    cudaGetSymbolAddress((void**)&Wml_h, g_Wml_hi); cudaGetSymbolAddress((void**)&Wml_l, g_Wml_lo);
    cudaGetSymbolAddress((void**)&bml,   g_bml);
    cudaGetSymbolAddress((void**)&bscale, g_bscale);
    cudaGetSymbolAddress((void**)&part,  g_part);

    cudaFuncSetAttribute(gemm_bf16x3,
                         cudaFuncAttributeMaxDynamicSharedMemorySize, SMEM_GEMM);

    build_scale_kernel<<<8, 256>>>(fw, kp);
    build_D_kernel<<<(DIMN * DIMN) / 256, 256>>>();

    convert_split<<<(BATCH * DIMN / 8 + 255) / 256, 256>>>(x, x_h, x_l, BATCH * DIMN);
    convert_split<<<(1024 * DIMN / 8 + 255) / 256, 256>>>(W1, W1_h, W1_l, 1024 * DIMN);
    convert_split<<<(512 * 1024 / 8 + 255) / 256, 256>>>(W2, W2_h, W2_l, 512 * 1024);
    convert_split<<<(256 * 512 / 8 + 255) / 256, 256>>>(Wmu, Wml_h, Wml_l, 256 * 512);
    convert_split<<<(256 * 512 / 8 + 255) / 256, 256>>>(Wlv, Wml_h + 256 * 512,
                                                        Wml_l + 256 * 512, 256 * 512);
    merge_bias<<<2, 256>>>(bmu, blv);

    const int nW = 1024 * DIMN;

    // A1[j][kf] = (sum_n W1[j][n] * D[kf][n]) * bscale[kf]   (split-K=4)
    gemm_bf16x3<<<dim3(16, 8, 4), 256, SMEM_GEMM>>>(
        W1_h, W1_l, Dm_h, Dm_l, nullptr, nullptr, nullptr, nullptr, nullptr,
        part, 1024, 2048, 2048, 512, 0);
    reduce4_split<<<(nW / 4 + 255) / 256, 256>>>(part, bscale, A1_h, A1_l, nW, 2048);

    // W1e[j][m] = sum_kf A1[j][kf] * Dt[m][kf]               (split-K=4)
    gemm_bf16x3<<<dim3(16, 8, 4), 256, SMEM_GEMM>>>(
        A1_h, A1_l, Dt_h, Dt_l, nullptr, nullptr, nullptr, nullptr, nullptr,
        part, 1024, 2048, 2048, 512, 0);
    reduce4_split<<<(nW / 4 + 255) / 256, 256>>>(part, nullptr, W1e_h, W1e_l, nW, 2048);

    // h1 = relu(x @ W1e^T + b1)
    gemm_bf16x3<<<dim3(8, 128, 1), 256, SMEM_GEMM>>>(
        x_h, x_l, W1e_h, W1e_l, b1, nullptr, h1_h, h1_l, nullptr, nullptr,
        BATCH, 1024, 2048, 2048, 1);
    // h2 = relu(h1 @ W2^T + b2)
    gemm_bf16x3<<<dim3(4, 128, 1), 256, SMEM_GEMM>>>(
        h1_h, h1_l, W2_h, W2_l, b2, nullptr, h2_h, h2_l, nullptr, nullptr,
        BATCH, 512, 1024, 1024, 1);
    // [mu | logvar] = h2 @ [Wmu;Wlv]^T + [bmu;blv]
    gemm_bf16x3<<<dim3(4, 128, 1), 256, SMEM_GEMM>>>(
        h2_h, h2_l, Wml_h, Wml_l, bml, nullptr, nullptr, nullptr, out, nullptr,
        BATCH, 512, 512, 512, 0);
}